// round 10
// baseline (speedup 1.0000x reference)
#include <cuda_runtime.h>

#define IC 1152
#define OC 10
#define ID 8
#define OD 16
#define BATCH 32
#define NI 8
#define NBLK (IC / NI)     // 144
#define THREADS 640        // 20 warps: thread = (c, b, od_half)
#define OUTSZ (BATCH * OC * OD)   // 5120
#define WROW (OC * ID)     // 80 weight rows (of 16 floats) per i

typedef unsigned long long ull;

__device__ float g_part[IC * OUTSZ];        // per-i contributions ar*rSh*h  (23.6MB)
__device__ float g_ar[BATCH * OC * IC];     // per-(b,c,i) unnormalized alpha (1.5MB)

__device__ __forceinline__ ull ffma2(ull a, ull b, ull c) {
    ull d; asm("fma.rn.f32x2 %0, %1, %2, %3;" : "=l"(d) : "l"(a), "l"(b), "l"(c)); return d;
}
__device__ __forceinline__ ull fmul2(ull a, ull b) {
    ull d; asm("mul.rn.f32x2 %0, %1, %2;" : "=l"(d) : "l"(a), "l"(b)); return d;
}
__device__ __forceinline__ ull fadd2(ull a, ull b) {
    ull d; asm("add.rn.f32x2 %0, %1, %2;" : "=l"(d) : "l"(a), "l"(b)); return d;
}
__device__ __forceinline__ ull pack2(float x, float y) {
    ull u; asm("mov.b64 %0, {%1, %2};" : "=l"(u) : "f"(x), "f"(y)); return u;
}
__device__ __forceinline__ void unpack2(ull u, float& x, float& y) {
    asm("mov.b64 {%0, %1}, %2;" : "=f"(x), "=f"(y) : "l"(u));
}
__device__ __forceinline__ float frcp(float x) {
    float y; asm("rcp.approx.f32 %0, %1;" : "=f"(y) : "f"(x)); return y;
}
__device__ __forceinline__ ull dot4(ull h0, ull h1, ull h2, ull h3,
                                    ull w0, ull w1, ull w2, ull w3) {
    ull p = fmul2(h0, w0);
    p = ffma2(h1, w1, p);
    p = ffma2(h2, w2, p);
    p = ffma2(h3, w3, p);
    return p;
}

__global__ __launch_bounds__(THREADS, 1) void caps_kernel(
    const float* __restrict__ x, const float* __restrict__ w, float* __restrict__ out_unused)
{
    __shared__ __align__(16) float ws_sm[NI * OC * ID * OD];  // all 8 i's, 40KB
    __shared__ float wsum_sm[NI * WROW];
    __shared__ float xn_sm[NI][ID][BATCH + 1];                // padded transpose

    const int t   = threadIdx.x;
    const int c   = t >> 6;          // output capsule: 2 warps per c
    const int b   = (t & 63) >> 1;   // batch
    const int odh = t & 1;           // od half
    const int i0  = blockIdx.x * NI;

    // ==== stage ALL weights: thread t owns row (ii,c,d)=t; row-sum in-thread ====
    {
        const float4* wr = (const float4*)(w + ((size_t)i0 * WROW + t) * OD);
        float4 a0 = wr[0], a1 = wr[1], a2 = wr[2], a3 = wr[3];
        float tot = (a0.x + a0.y + a0.z + a0.w) + (a1.x + a1.y + a1.z + a1.w)
                  + (a2.x + a2.y + a2.z + a2.w) + (a3.x + a3.y + a3.z + a3.w);
        float r = frcp(tot);
        float4* dst = (float4*)(ws_sm + t * OD);
        float4 s0, s1, s2, s3;
        s0.x = a0.x * r; s0.y = a0.y * r; s0.z = a0.z * r; s0.w = a0.w * r;
        s1.x = a1.x * r; s1.y = a1.y * r; s1.z = a1.z * r; s1.w = a1.w * r;
        s2.x = a2.x * r; s2.y = a2.y * r; s2.z = a2.z * r; s2.w = a2.w * r;
        s3.x = a3.x * r; s3.y = a3.y * r; s3.z = a3.z * r; s3.w = a3.w * r;
        dst[0] = s0; dst[1] = s1; dst[2] = s2; dst[3] = s3;
        wsum_sm[t] = tot;
    }
    // ==== stage ALL x: t<512: thread = (b, q) with q = (ii, d-half) ====
    if (t < 512) {
        int bb = t >> 4, q = t & 15;
        float4 xv = *(const float4*)(x + (size_t)bb * (IC * ID) + (size_t)i0 * ID + q * 4);
        float ps  = xv.x + xv.y + xv.z + xv.w;
        float tot = ps + __shfl_xor_sync(0xffffffffu, ps, 1);
        float r = frcp(tot);
        int ii = q >> 1, dh = (q & 1) * 4;
        xn_sm[ii][dh + 0][bb] = xv.x * r;
        xn_sm[ii][dh + 1][bb] = xv.y * r;
        xn_sm[ii][dh + 2][bb] = xv.z * r;
        xn_sm[ii][dh + 3][bb] = xv.w * r;
    }
    __syncthreads();   // the ONLY barrier in this kernel

    float* gdst = g_part + (size_t)i0 * OUTSZ + b * (OC * OD) + c * OD + odh * 8;
    float* ardst = g_ar + (size_t)b * (OC * IC) + (size_t)c * IC + i0;

    #pragma unroll 1
    for (int ii = 0; ii < NI; ii++) {
        const float* wc = ws_sm + ii * (OC * ID * OD) + c * (ID * OD) + odh * 8;
        float xn[8];
        #pragma unroll
        for (int d = 0; d < 8; d++) xn[d] = xn_sm[ii][d][b];

        // ---- iteration 1: h1[o] = Σ_d xn[d]·ŵ[d,o]  (h0 uniform) ----
        ull h[4];
        {
            const ulonglong2* wr = (const ulonglong2*)wc;
            ulonglong2 wa = wr[0], wb2 = wr[1];
            ull xp = pack2(xn[0], xn[0]);
            h[0] = fmul2(xp, wa.x);
            h[1] = fmul2(xp, wa.y);
            h[2] = fmul2(xp, wb2.x);
            h[3] = fmul2(xp, wb2.y);
        }
        #pragma unroll
        for (int d = 1; d < 8; d++) {
            ull xp = pack2(xn[d], xn[d]);
            const ulonglong2* wr = (const ulonglong2*)(wc + d * 16);
            ulonglong2 wa = wr[0], wb2 = wr[1];
            h[0] = ffma2(xp, wa.x,  h[0]);
            h[1] = ffma2(xp, wa.y,  h[1]);
            h[2] = ffma2(xp, wb2.x, h[2]);
            h[3] = ffma2(xp, wb2.y, h[3]);
        }

        // ---- iterations 2..5, fused den/f passes (scale-invariant ⇒ no renorm) ----
        #pragma unroll 1
        for (int it = 0; it < 4; it++) {
            ull f[4];
            #pragma unroll
            for (int j = 0; j < 4; j++) f[j] = pack2(0.f, 0.f);
            #pragma unroll
            for (int d = 0; d < 8; d++) {
                const ulonglong2* wr = (const ulonglong2*)(wc + d * 16);
                ulonglong2 wa = wr[0], wb2 = wr[1];
                ull pp = dot4(h[0], h[1], h[2], h[3], wa.x, wa.y, wb2.x, wb2.y);
                float pa, pb; unpack2(pp, pa, pb);
                float hd  = pa + pb;
                float den = hd + __shfl_xor_sync(0xffffffffu, hd, 1);
                float xr  = xn[d] * frcp(den);
                ull xp = pack2(xr, xr);
                f[0] = ffma2(xp, wa.x,  f[0]);
                f[1] = ffma2(xp, wa.y,  f[1]);
                f[2] = ffma2(xp, wb2.x, f[2]);
                f[3] = ffma2(xp, wb2.y, f[3]);
            }
            #pragma unroll
            for (int j = 0; j < 4; j++) h[j] = fmul2(h[j], f[j]);
        }

        // ---- epilogue: alpha numerator from final denominators ----
        float A = 0.f;
        #pragma unroll
        for (int d = 0; d < 8; d++) {
            const ulonglong2* wr = (const ulonglong2*)(wc + d * 16);
            ulonglong2 wa = wr[0], wb2 = wr[1];
            ull pp = dot4(h[0], h[1], h[2], h[3], wa.x, wa.y, wb2.x, wb2.y);
            float pa, pb; unpack2(pp, pa, pb);
            float hd  = pa + pb;
            float den = hd + __shfl_xor_sync(0xffffffffu, hd, 1);
            A = fmaf(xn[d] * wsum_sm[ii * WROW + c * 8 + d], den, A);
        }
        ull s2 = fadd2(fadd2(h[0], h[1]), fadd2(h[2], h[3]));
        float sa, sb; unpack2(s2, sa, sb);
        float shh = sa + sb;
        float Sh  = shh + __shfl_xor_sync(0xffffffffu, shh, 1);
        float rSh = frcp(Sh);
        float ar  = A * rSh;           // unnormalized alpha (pre Σ_c division)
        if (odh == 0) ardst[ii] = ar;
        // store g = ar * rSh * h  (= alpha_unnorm * h_normalized); Σ_c handled in reduce
        float gs = ar * rSh;
        ull gp = pack2(gs, gs);
        ulonglong2 s0, s1;
        s0.x = fmul2(gp, h[0]); s0.y = fmul2(gp, h[1]);
        s1.x = fmul2(gp, h[2]); s1.y = fmul2(gp, h[3]);
        float* dst = gdst + (size_t)ii * OUTSZ;
        ((ulonglong2*)dst)[0] = s0;
        ((ulonglong2*)dst)[1] = s1;
        // no barrier: warps fully independent from here on
    }
}

// Reduce v4: grid = 320 blocks (b,c), 512 threads.
// Phase 1: rS[i] = 1/Σ_c ar[b,c,i]  (coalesced over i, L2-resident)
// Phase 2: out[b,c,od] = Σ_i g_part[i,b,c,od] * rS[i]
__global__ __launch_bounds__(512, 2) void caps_reduce_kernel(float* __restrict__ out) {
    __shared__ float rS_sm[IC];
    __shared__ float red[32][16];
    const int t = threadIdx.x;
    const int b = blockIdx.x / OC;
    const int c = blockIdx.x % OC;

    for (int i = t; i < IC; i += 512) {
        const float* ap = g_ar + (size_t)b * (OC * IC) + i;
        float s = 0.f;
        #pragma unroll
        for (int cc = 0; cc < OC; cc++) s += __ldcg(ap + (size_t)cc * IC);
        rS_sm[i] = frcp(s);
    }
    __syncthreads();

    const int od = t & 15;
    const int ks = t >> 4;              // 0..31
    const float* src = g_part + (size_t)b * (OC * OD) + c * OD + od;
    float s = 0.f;
    #pragma unroll 6
    for (int k = 0; k < 36; k++) {      // i = ks + 32*k
        int i = ks + 32 * k;
        s = fmaf(__ldcg(src + (size_t)i * OUTSZ), rS_sm[i], s);
    }
    red[ks][od] = s;
    __syncthreads();
    if (t < 16) {
        float acc = 0.f;
        #pragma unroll
        for (int q = 0; q < 32; q++) acc += red[q][t];
        out[b * (OC * OD) + c * OD + t] = acc;
    }
}

extern "C" void kernel_launch(void* const* d_in, const int* in_sizes, int n_in,
                              void* d_out, int out_size)
{
    const float* x = (const float*)d_in[0];
    const float* w = (const float*)d_in[1];
    if (n_in >= 2 && in_sizes[0] == IC * OC * ID * OD && in_sizes[1] == BATCH * IC * ID) {
        x = (const float*)d_in[1];
        w = (const float*)d_in[0];
    }
    float* out = (float*)d_out;

    caps_kernel<<<NBLK, THREADS>>>(x, w, out);
    caps_reduce_kernel<<<BATCH * OC, 512>>>(out);
}

// round 12
// speedup vs baseline: 1.1617x; 1.1617x over previous
#include <cuda_runtime.h>
#include <cuda_bf16.h>

#define IC 1152
#define OC 10
#define ID 8
#define OD 16
#define BATCH 32
#define NI 8
#define NBLK (IC / NI)     // 144
#define THREADS 640        // 20 warps: thread = (c, b, od_half)
#define OUTSZ (BATCH * OC * OD)   // 5120
#define WROW (OC * ID)     // 80 weight rows (of 16 floats) per i

typedef unsigned long long ull;

__device__ __nv_bfloat16 g_part[BATCH * OC * IC * OD];  // per-i contributions, 11.8MB
__device__ float g_rs[BATCH * IC];                      // rS = 1/Σ_c ar, 147KB

__device__ __forceinline__ ull ffma2(ull a, ull b, ull c) {
    ull d; asm("fma.rn.f32x2 %0, %1, %2, %3;" : "=l"(d) : "l"(a), "l"(b), "l"(c)); return d;
}
__device__ __forceinline__ ull fmul2(ull a, ull b) {
    ull d; asm("mul.rn.f32x2 %0, %1, %2;" : "=l"(d) : "l"(a), "l"(b)); return d;
}
__device__ __forceinline__ ull fadd2(ull a, ull b) {
    ull d; asm("add.rn.f32x2 %0, %1, %2;" : "=l"(d) : "l"(a), "l"(b)); return d;
}
__device__ __forceinline__ ull pack2(float x, float y) {
    ull u; asm("mov.b64 %0, {%1, %2};" : "=l"(u) : "f"(x), "f"(y)); return u;
}
__device__ __forceinline__ void unpack2(ull u, float& x, float& y) {
    asm("mov.b64 {%0, %1}, %2;" : "=f"(x), "=f"(y) : "l"(u));
}
__device__ __forceinline__ float frcp(float x) {
    float y; asm("rcp.approx.f32 %0, %1;" : "=f"(y) : "f"(x)); return y;
}
// f32x2 -> bf16x2 with lane order preserved (lo stays lo)
__device__ __forceinline__ unsigned cvt_bf16x2(ull f32x2) {
    float lo, hi; unpack2(f32x2, lo, hi);
    unsigned r;
    asm("cvt.rn.bf16x2.f32 %0, %1, %2;" : "=r"(r) : "f"(hi), "f"(lo));
    return r;
}
__device__ __forceinline__ ull dot4(ull h0, ull h1, ull h2, ull h3,
                                    ull w0, ull w1, ull w2, ull w3) {
    ull p = fmul2(h0, w0);
    p = ffma2(h1, w1, p);
    p = ffma2(h2, w2, p);
    p = ffma2(h3, w3, p);
    return p;
}

__global__ __launch_bounds__(THREADS, 1) void caps_kernel(
    const float* __restrict__ x, const float* __restrict__ w, float* __restrict__ out_unused)
{
    __shared__ __align__(16) float ws_sm[NI * OC * ID * OD];  // all 8 i's, 40KB
    __shared__ float wsum_sm[NI * WROW];
    __shared__ float xn_sm[NI][ID][BATCH + 1];                // padded transpose
    __shared__ float ar_sm[NI][OC][BATCH];                    // unnormalized alpha

    const int t   = threadIdx.x;
    const int c   = t >> 6;          // output capsule: 2 warps per c
    const int b   = (t & 63) >> 1;   // batch
    const int odh = t & 1;           // od half
    const int i0  = blockIdx.x * NI;

    // ==== stage ALL weights: thread t owns row (ii,c,d)=t; row-sum in-thread ====
    {
        const float4* wr = (const float4*)(w + ((size_t)i0 * WROW + t) * OD);
        float4 a0 = wr[0], a1 = wr[1], a2 = wr[2], a3 = wr[3];
        float tot = (a0.x + a0.y + a0.z + a0.w) + (a1.x + a1.y + a1.z + a1.w)
                  + (a2.x + a2.y + a2.z + a2.w) + (a3.x + a3.y + a3.z + a3.w);
        float r = frcp(tot);
        float4* dst = (float4*)(ws_sm + t * OD);
        float4 s0, s1, s2, s3;
        s0.x = a0.x * r; s0.y = a0.y * r; s0.z = a0.z * r; s0.w = a0.w * r;
        s1.x = a1.x * r; s1.y = a1.y * r; s1.z = a1.z * r; s1.w = a1.w * r;
        s2.x = a2.x * r; s2.y = a2.y * r; s2.z = a2.z * r; s2.w = a2.w * r;
        s3.x = a3.x * r; s3.y = a3.y * r; s3.z = a3.z * r; s3.w = a3.w * r;
        dst[0] = s0; dst[1] = s1; dst[2] = s2; dst[3] = s3;
        wsum_sm[t] = tot;
    }
    // ==== stage ALL x: t<512: thread = (b, q) with q = (ii, d-half) ====
    if (t < 512) {
        int bb = t >> 4, q = t & 15;
        float4 xv = *(const float4*)(x + (size_t)bb * (IC * ID) + (size_t)i0 * ID + q * 4);
        float ps  = xv.x + xv.y + xv.z + xv.w;
        float tot = ps + __shfl_xor_sync(0xffffffffu, ps, 1);
        float r = frcp(tot);
        int ii = q >> 1, dh = (q & 1) * 4;
        xn_sm[ii][dh + 0][bb] = xv.x * r;
        xn_sm[ii][dh + 1][bb] = xv.y * r;
        xn_sm[ii][dh + 2][bb] = xv.z * r;
        xn_sm[ii][dh + 3][bb] = xv.w * r;
    }
    __syncthreads();   // staging barrier

    // g_part layout: [b][c][i][od], bf16
    __nv_bfloat16* gbase = g_part
        + (((size_t)b * OC + c) * IC + i0) * OD + odh * 8;

    #pragma unroll 1
    for (int ii = 0; ii < NI; ii++) {
        const float* wc = ws_sm + ii * (OC * ID * OD) + c * (ID * OD) + odh * 8;
        float xn[8];
        #pragma unroll
        for (int d = 0; d < 8; d++) xn[d] = xn_sm[ii][d][b];

        // ---- iteration 1: h1[o] = Σ_d xn[d]·ŵ[d,o]  (h0 uniform) ----
        ull h[4];
        {
            const ulonglong2* wr = (const ulonglong2*)wc;
            ulonglong2 wa = wr[0], wb2 = wr[1];
            ull xp = pack2(xn[0], xn[0]);
            h[0] = fmul2(xp, wa.x);
            h[1] = fmul2(xp, wa.y);
            h[2] = fmul2(xp, wb2.x);
            h[3] = fmul2(xp, wb2.y);
        }
        #pragma unroll
        for (int d = 1; d < 8; d++) {
            ull xp = pack2(xn[d], xn[d]);
            const ulonglong2* wr = (const ulonglong2*)(wc + d * 16);
            ulonglong2 wa = wr[0], wb2 = wr[1];
            h[0] = ffma2(xp, wa.x,  h[0]);
            h[1] = ffma2(xp, wa.y,  h[1]);
            h[2] = ffma2(xp, wb2.x, h[2]);
            h[3] = ffma2(xp, wb2.y, h[3]);
        }

        // ---- iterations 2..5, fused den/f passes (scale-invariant ⇒ no renorm) ----
        #pragma unroll 1
        for (int it = 0; it < 4; it++) {
            ull f[4];
            #pragma unroll
            for (int j = 0; j < 4; j++) f[j] = pack2(0.f, 0.f);
            #pragma unroll
            for (int d = 0; d < 8; d++) {
                const ulonglong2* wr = (const ulonglong2*)(wc + d * 16);
                ulonglong2 wa = wr[0], wb2 = wr[1];
                ull pp = dot4(h[0], h[1], h[2], h[3], wa.x, wa.y, wb2.x, wb2.y);
                float pa, pb; unpack2(pp, pa, pb);
                float hd  = pa + pb;
                float den = hd + __shfl_xor_sync(0xffffffffu, hd, 1);
                float xr  = xn[d] * frcp(den);
                ull xp = pack2(xr, xr);
                f[0] = ffma2(xp, wa.x,  f[0]);
                f[1] = ffma2(xp, wa.y,  f[1]);
                f[2] = ffma2(xp, wb2.x, f[2]);
                f[3] = ffma2(xp, wb2.y, f[3]);
            }
            #pragma unroll
            for (int j = 0; j < 4; j++) h[j] = fmul2(h[j], f[j]);
        }

        // ---- epilogue: alpha numerator from final denominators ----
        float A = 0.f;
        #pragma unroll
        for (int d = 0; d < 8; d++) {
            const ulonglong2* wr = (const ulonglong2*)(wc + d * 16);
            ulonglong2 wa = wr[0], wb2 = wr[1];
            ull pp = dot4(h[0], h[1], h[2], h[3], wa.x, wa.y, wb2.x, wb2.y);
            float pa, pb; unpack2(pp, pa, pb);
            float hd  = pa + pb;
            float den = hd + __shfl_xor_sync(0xffffffffu, hd, 1);
            A = fmaf(xn[d] * wsum_sm[ii * WROW + c * 8 + d], den, A);
        }
        ull s2 = fadd2(fadd2(h[0], h[1]), fadd2(h[2], h[3]));
        float sa, sb; unpack2(s2, sa, sb);
        float shh = sa + sb;
        float Sh  = shh + __shfl_xor_sync(0xffffffffu, shh, 1);
        float rSh = frcp(Sh);
        float ar  = A * rSh;           // unnormalized alpha
        if (odh == 0) ar_sm[ii][c][b] = ar;
        // store g = ar * rSh * h as bf16x4 pairs (16B STG)
        float gs = ar * rSh;
        ull gp = pack2(gs, gs);
        uint4 pkt;
        pkt.x = cvt_bf16x2(fmul2(gp, h[0]));
        pkt.y = cvt_bf16x2(fmul2(gp, h[1]));
        pkt.z = cvt_bf16x2(fmul2(gp, h[2]));
        pkt.w = cvt_bf16x2(fmul2(gp, h[3]));
        *(uint4*)(gbase + (size_t)ii * OD) = pkt;
        // no per-ii barrier: warps fully independent
    }

    // ---- end-of-block: rS(b, i) = 1/Σ_c ar  (all c resident in this block) ----
    __syncthreads();
    if (t < NI * BATCH) {
        int ii = t >> 5, bb = t & 31;
        float S = 0.f;
        #pragma unroll
        for (int cc = 0; cc < OC; cc++) S += ar_sm[ii][cc][bb];
        g_rs[(size_t)bb * IC + i0 + ii] = frcp(S);
    }
}

// Reduce v5: grid = 320 blocks (b,c) x 256 threads (ks 0..31, odp 0..7).
// warp reads 4 consecutive i-rows x 32B = 128B fully coalesced, L2-resident bf16.
__global__ __launch_bounds__(256, 4) void caps_reduce_kernel(float* __restrict__ out) {
    __shared__ float rS_sm[IC];
    __shared__ float2 red[32][8];
    const int t = threadIdx.x;
    const int b = blockIdx.x / OC;
    const int c = blockIdx.x % OC;

    for (int i = t; i < IC; i += 256)
        rS_sm[i] = g_rs[(size_t)b * IC + i];
    __syncthreads();

    const int ks  = t >> 3;   // 0..31: i-slice
    const int odp = t & 7;    // od pair
    const unsigned* src = (const unsigned*)g_part + ((size_t)b * OC + c) * IC * 8 + odp;
    float2 acc = make_float2(0.f, 0.f);
    #pragma unroll 12
    for (int k = 0; k < 36; k++) {
        int i = ks + 32 * k;
        unsigned v = __ldcg(src + (size_t)i * 8);
        __nv_bfloat162 bv = *(__nv_bfloat162*)&v;
        float2 fv = __bfloat1622float2(bv);
        float r = rS_sm[i];
        acc.x = fmaf(fv.x, r, acc.x);
        acc.y = fmaf(fv.y, r, acc.y);
    }
    red[ks][odp] = acc;
    __syncthreads();
    if (t < 8) {
        float2 a = make_float2(0.f, 0.f);
        #pragma unroll
        for (int q = 0; q < 32; q++) {
            a.x += red[q][t].x;
            a.y += red[q][t].y;
        }
        out[b * (OC * OD) + c * OD + t * 2]     = a.x;
        out[b * (OC * OD) + c * OD + t * 2 + 1] = a.y;
    }
}

extern "C" void kernel_launch(void* const* d_in, const int* in_sizes, int n_in,
                              void* d_out, int out_size)
{
    const float* x = (const float*)d_in[0];
    const float* w = (const float*)d_in[1];
    if (n_in >= 2 && in_sizes[0] == IC * OC * ID * OD && in_sizes[1] == BATCH * IC * ID) {
        x = (const float*)d_in[1];
        w = (const float*)d_in[0];
    }
    float* out = (float*)d_out;

    caps_kernel<<<NBLK, THREADS>>>(x, w, out);
    caps_reduce_kernel<<<BATCH * OC, 256>>>(out);
}